// round 15
// baseline (speedup 1.0000x reference)
#include <cuda_runtime.h>
#include <cuda_fp16.h>

// Problem constants (fixed by the reference setup)
#define B_ 4
#define C_ 3
#define H_ 512
#define W_ 960
#define HW_ (H_ * W_)

// Tile geometry: 64x16 pixels per block, 256 threads, 4 pixels/thread (along y)
#define TW 64
#define TH 16
#define NTHREADS 256
#define SWU (TW + 13)         // 77 used cols: halo 6 left, 7 right
#define PA 80                 // plane-A pitch in uint2 texels; 80 % 16 == 0 -> dy-invariant banks
#define PB 96                 // plane-B pitch in 4B words;   96 % 32 == 0 -> dy-invariant banks
#define SH (TH + 13)          // 29 rows: halo 6 top, 7 bottom
#define NTEX (SWU * SH)       // texels to stage

__global__ void __launch_bounds__(NTHREADS, 5)
fi_tiled_h15_kernel(const float* __restrict__ inp,
                    const float* __restrict__ flow,
                    const float* __restrict__ filt,
                    float* __restrict__ out)
{
    // Plane A: (c0[x],c1[x] | c0[x+1],c1[x+1]) fp16 quad -> one LDS.64 = 2 taps, 2 channels
    // Plane B: (c2[x], c2[x+1]) fp16 pair      -> one LDS.32 = 2 taps, 1 channel
    __shared__ uint2    smA[PA * SH];   // 18.6 KB
    __shared__ unsigned smB[PB * SH];   // 11.1 KB

    const int x0 = blockIdx.x * TW;
    const int y0 = blockIdx.y * TH;
    const int b  = blockIdx.z;
    const int tid = threadIdx.x;

    const float* __restrict__ ibase = inp + (size_t)b * C_ * HW_;

    // ---- stage tile + halo (border clamp baked in, fp32 -> fp16) ----
    #pragma unroll 3
    for (int idx = tid; idx < NTEX; idx += NTHREADS) {
        const int j = idx / SWU;
        const int i = idx - j * SWU;
        const int gy  = min(max(y0 - 6 + j, 0), H_ - 1);
        const int gx  = min(max(x0 - 6 + i, 0), W_ - 1);
        const int gx1 = min(max(x0 - 5 + i, 0), W_ - 1);   // clamp of (unclamped gx)+1
        const int rowg = gy * W_;
        const float v0  = ibase[rowg + gx];
        const float v0n = ibase[rowg + gx1];
        const float v1  = ibase[rowg + gx  + HW_];
        const float v1n = ibase[rowg + gx1 + HW_];
        const float v2  = ibase[rowg + gx  + 2 * HW_];
        const float v2n = ibase[rowg + gx1 + 2 * HW_];
        const __half2 alo = __floats2half2_rn(v0, v1);
        const __half2 ahi = __floats2half2_rn(v0n, v1n);
        const __half2 bp  = __floats2half2_rn(v2, v2n);
        uint2 ua;
        ua.x = *reinterpret_cast<const unsigned*>(&alo);
        ua.y = *reinterpret_cast<const unsigned*>(&ahi);
        smA[j * PA + i] = ua;
        smB[j * PB + i] = *reinterpret_cast<const unsigned*>(&bp);
    }
    __syncthreads();

    const int x     = x0 + (tid & 63);
    const int tyg   = tid >> 6;            // 0..3
    const int ybase = y0 + tyg * 4;

    const float* __restrict__ flowx = flow + ((size_t)b * 2 + 0) * HW_;
    const float* __restrict__ flowy = flow + ((size_t)b * 2 + 1) * HW_;
    const float* __restrict__ fbb   = filt + (size_t)b * 16 * HW_;
    float* __restrict__ obb         = out  + (size_t)b * C_ * HW_;

    // ---- hoist ALL flow loads ----
    float fxv[4], fyv[4];
    #pragma unroll
    for (int k = 0; k < 4; k++) {
        fxv[k] = __ldcs(flowx + (ybase + k) * W_ + x);
        fyv[k] = __ldcs(flowy + (ybase + k) * W_ + x);
    }

    #pragma unroll
    for (int k = 0; k < 4; k++) {
        const int y   = ybase + k;
        const int pix = y * W_ + x;

        const float cfx = fxv[k], cfy = fyv[k];
        const float x2 = (float)x + cfx;
        const float y2 = (float)y + cfy;

        const bool valid =
            (x2 >= 0.0f) && (x2 <= (float)(W_ - 1)) &&
            (y2 >= 0.0f) && (y2 <= (float)(H_ - 1)) &&
            (fabsf(cfx) < (float)W_ * 0.5f) &&
            (fabsf(cfy) < (float)H_ * 0.5f);
        const float validf = valid ? 1.0f : 0.0f;

        const int   ix = __float2int_rd(x2);
        const int   iy = __float2int_rd(y2);
        const float a  = x2 - (float)ix;
        const float bt = y2 - (float)iy;

        const float wTL = (1.0f - a) * (1.0f - bt);
        const float wTR = a * (1.0f - bt);
        const float wBL = (1.0f - a) * bt;
        const float wBR = a * bt;

        // ---- preload 16 filter taps ----
        float f[16];
        const float* fb = fbb + pix;
        #pragma unroll
        for (int t = 0; t < 16; t++) f[t] = __ldcs(fb + t * HW_);

        // ---- window coords, clamped into the staged halo (branchless) ----
        const int ly  = iy - y0 + 5;
        const int lx  = ix - x0 + 5;
        const int lyc = min(max(ly, 0), SH - 5);
        const int lxc = min(max(lx, 0), SWU - 5);
        const bool fixup = valid && ((lyc != ly) || (lxc != lx));

        float r0 = 0.0f, r1 = 0.0f, r2 = 0.0f;

        // ---- fast path: 25 taps, row-pipelined; A: 3 LDS.64, B: 3 LDS.32 per row ----
        {
            const int baseA = lyc * PA + lxc;
            const int baseB = lyc * PB + lxc;

            uint2    curA[3], nxtA[3];
            unsigned curB[3], nxtB[3];
            #pragma unroll
            for (int p = 0; p < 3; p++) curA[p] = smA[baseA + 2 * p];
            #pragma unroll
            for (int p = 0; p < 3; p++) curB[p] = smB[baseB + 2 * p];

            #pragma unroll
            for (int r = 0; r < 5; r++) {
                if (r < 4) {
                    const int nbA = baseA + (r + 1) * PA;
                    const int nbB = baseB + (r + 1) * PB;
                    #pragma unroll
                    for (int p = 0; p < 3; p++) nxtA[p] = smA[nbA + 2 * p];
                    #pragma unroll
                    for (int p = 0; p < 3; p++) nxtB[p] = smB[nbB + 2 * p];
                }

                // per-row weights (fp32)
                float w[5];
                #pragma unroll
                for (int c = 0; c < 5; c++) {
                    float ww = 0.0f;
                    if (r < 4 && c < 4)  ww += wTL * f[r * 4 + c];
                    if (r < 4 && c >= 1) ww += wTR * f[r * 4 + c - 1];
                    if (r >= 1 && c < 4) ww += wBL * f[(r - 1) * 4 + c];
                    if (r >= 1 && c >= 1)ww += wBR * f[(r - 1) * 4 + c - 1];
                    w[c] = ww;
                }

                // channels 0,1: 3 paired texels; pair p covers cols 2p, 2p+1
                __half2 acc01 = __floats2half2_rn(0.0f, 0.0f);
                #pragma unroll
                for (int p = 0; p < 3; p++) {
                    const __half2 tlo = *reinterpret_cast<const __half2*>(&curA[p].x);
                    acc01 = __hfma2(__float2half2_rn(w[2 * p]), tlo, acc01);
                    if (p < 2) {
                        const __half2 thi = *reinterpret_cast<const __half2*>(&curA[p].y);
                        acc01 = __hfma2(__float2half2_rn(w[2 * p + 1]), thi, acc01);
                    }
                }

                // channel 2: paired taps, weight pairs (w0,w1)(w2,w3)(w4,0)
                __half2 accB = __floats2half2_rn(0.0f, 0.0f);
                {
                    const __half2 wp0 = __floats2half2_rn(w[0], w[1]);
                    const __half2 wp1 = __floats2half2_rn(w[2], w[3]);
                    const __half2 wp2 = __floats2half2_rn(w[4], 0.0f);
                    accB = __hfma2(wp0, *reinterpret_cast<const __half2*>(&curB[0]), accB);
                    accB = __hfma2(wp1, *reinterpret_cast<const __half2*>(&curB[1]), accB);
                    accB = __hfma2(wp2, *reinterpret_cast<const __half2*>(&curB[2]), accB);
                }

                const float2 p01 = __half22float2(acc01);
                const float2 pb  = __half22float2(accB);
                r0 += p01.x;
                r1 += p01.y;
                r2 += pb.x + pb.y;

                if (r < 4) {
                    #pragma unroll
                    for (int p = 0; p < 3; p++) curA[p] = nxtA[p];
                    #pragma unroll
                    for (int p = 0; p < 3; p++) curB[p] = nxtB[p];
                }
            }
        }

        // ---- rare fix-up (warp-uniformly skipped ~always): fp32 global gathers ----
        if (__any_sync(0xffffffffu, fixup)) {
            if (fixup) {
                r0 = 0.0f; r1 = 0.0f; r2 = 0.0f;
                #pragma unroll 1
                for (int r = 0; r < 5; r++) {
                    const int yy = min(max(iy - 1 + r, 0), H_ - 1);
                    const float* g0 = ibase + yy * W_;
                    #pragma unroll 1
                    for (int c = 0; c < 5; c++) {
                        float w = 0.0f;
                        if (r < 4 && c < 4)  w += wTL * f[r * 4 + c];
                        if (r < 4 && c >= 1) w += wTR * f[r * 4 + c - 1];
                        if (r >= 1 && c < 4) w += wBL * f[(r - 1) * 4 + c];
                        if (r >= 1 && c >= 1)w += wBR * f[(r - 1) * 4 + c - 1];

                        const int xo = min(max(ix - 1 + c, 0), W_ - 1);
                        r0 += w * __ldg(g0 + xo);
                        r1 += w * __ldg(g0 + xo + HW_);
                        r2 += w * __ldg(g0 + xo + 2 * HW_);
                    }
                }
            }
        }

        float* ob = obb + pix;
        __stcs(ob,            r0 * validf);
        __stcs(ob + HW_,      r1 * validf);
        __stcs(ob + 2 * HW_,  r2 * validf);
    }
}

extern "C" void kernel_launch(void* const* d_in, const int* in_sizes, int n_in,
                              void* d_out, int out_size)
{
    const float* teninput  = (const float*)d_in[0];
    const float* tenflow   = (const float*)d_in[1];
    const float* tenfilter = (const float*)d_in[2];
    float* out = (float*)d_out;

    dim3 grid(W_ / TW, H_ / TH, B_);   // 15 x 32 x 4
    fi_tiled_h15_kernel<<<grid, NTHREADS>>>(teninput, tenflow, tenfilter, out);
}

// round 16
// speedup vs baseline: 1.0914x; 1.0914x over previous
#include <cuda_runtime.h>
#include <cuda_fp16.h>

// Problem constants (fixed by the reference setup)
#define B_ 4
#define C_ 3
#define H_ 512
#define W_ 960
#define HW_ (H_ * W_)

// Tile geometry: 64x16 pixels per block, 256 threads, 4 pixels/thread (along y)
#define TW 64
#define TH 16
#define NTHREADS 256
#define SWU (TW + 13)         // 77 used cols: halo 6 left, 7 right
#define PU 96                 // plane pitch in 4B words; 96 % 32 == 0 -> bank hash dy-invariant
#define SH (TH + 13)          // 29 rows: halo 6 top, 7 bottom
#define NTEX (SWU * SH)       // texels to stage (scalar path)
#define NPAIR (SH * 39)       // texel pairs (vector path, 39 pairs = 78 cols)

__global__ void __launch_bounds__(NTHREADS, 5)
fi_tiled_h16_kernel(const float* __restrict__ inp,
                    const float* __restrict__ flow,
                    const float* __restrict__ filt,
                    float* __restrict__ out)
{
    // Plane A: (half c0, half c1) per texel.  Plane B: (half c2[x], half c2[x+1]).
    __shared__ unsigned smA[PU * SH];   // 11.1 KB
    __shared__ unsigned smB[PU * SH];   // 11.1 KB

    const int x0 = blockIdx.x * TW;
    const int y0 = blockIdx.y * TH;
    const int b  = blockIdx.z;
    const int tid = threadIdx.x;

    const float* __restrict__ ibase = inp + (size_t)b * C_ * HW_;

    // ---- stage tile + halo (fp32 -> fp16); vectorized path for interior blocks ----
    const bool interior = (x0 >= 6) && (x0 + TW + 8 <= W_) &&
                          (y0 >= 6) && (y0 + TH + 7 <= H_);
    if (interior) {
        // no clamping anywhere; 2 texels per iteration via 8B loads/stores
        #pragma unroll 2
        for (int pidx = tid; pidx < NPAIR; pidx += NTHREADS) {
            const int j = pidx / 39;
            const int i = (pidx - j * 39) * 2;
            const int g = (y0 - 6 + j) * W_ + (x0 - 6 + i);
            const float2 v0 = *reinterpret_cast<const float2*>(ibase + g);
            const float2 v1 = *reinterpret_cast<const float2*>(ibase + g + HW_);
            const float2 v2 = *reinterpret_cast<const float2*>(ibase + g + 2 * HW_);
            const float  v2c = ibase[g + 2 * HW_ + 2];
            const __half2 a0 = __floats2half2_rn(v0.x, v1.x);
            const __half2 a1 = __floats2half2_rn(v0.y, v1.y);
            const __half2 b0 = __floats2half2_rn(v2.x, v2.y);
            const __half2 b1 = __floats2half2_rn(v2.y, v2c);
            uint2 ua, ub;
            ua.x = *reinterpret_cast<const unsigned*>(&a0);
            ua.y = *reinterpret_cast<const unsigned*>(&a1);
            ub.x = *reinterpret_cast<const unsigned*>(&b0);
            ub.y = *reinterpret_cast<const unsigned*>(&b1);
            *reinterpret_cast<uint2*>(&smA[j * PU + i]) = ua;   // 8B-aligned: i even, PU even
            *reinterpret_cast<uint2*>(&smB[j * PU + i]) = ub;
        }
    } else {
        // border blocks: scalar path with clamp baked in (r14-proven)
        #pragma unroll 3
        for (int idx = tid; idx < NTEX; idx += NTHREADS) {
            const int j = idx / SWU;
            const int i = idx - j * SWU;
            const int gy  = min(max(y0 - 6 + j, 0), H_ - 1);
            const int gx  = min(max(x0 - 6 + i, 0), W_ - 1);
            const int gx1 = min(max(x0 - 5 + i, 0), W_ - 1);
            const int rowg = gy * W_;
            const float v0  = ibase[rowg + gx];
            const float v1  = ibase[rowg + gx + HW_];
            const float v2  = ibase[rowg + gx + 2 * HW_];
            const float v2n = ibase[rowg + gx1 + 2 * HW_];
            const __half2 a  = __floats2half2_rn(v0, v1);
            const __half2 bb = __floats2half2_rn(v2, v2n);
            smA[j * PU + i] = *reinterpret_cast<const unsigned*>(&a);
            smB[j * PU + i] = *reinterpret_cast<const unsigned*>(&bb);
        }
    }
    __syncthreads();

    const int x     = x0 + (tid & 63);
    const int tyg   = tid >> 6;            // 0..3
    const int ybase = y0 + tyg * 4;

    const float* __restrict__ flowx = flow + ((size_t)b * 2 + 0) * HW_;
    const float* __restrict__ flowy = flow + ((size_t)b * 2 + 1) * HW_;
    const float* __restrict__ fbb   = filt + (size_t)b * 16 * HW_;
    float* __restrict__ obb         = out  + (size_t)b * C_ * HW_;

    // ---- hoist ALL flow loads ----
    float fxv[4], fyv[4];
    #pragma unroll
    for (int k = 0; k < 4; k++) {
        fxv[k] = __ldcs(flowx + (ybase + k) * W_ + x);
        fyv[k] = __ldcs(flowy + (ybase + k) * W_ + x);
    }

    #pragma unroll
    for (int k = 0; k < 4; k++) {
        const int y   = ybase + k;
        const int pix = y * W_ + x;

        const float cfx = fxv[k], cfy = fyv[k];
        const float x2 = (float)x + cfx;
        const float y2 = (float)y + cfy;

        const bool valid =
            (x2 >= 0.0f) && (x2 <= (float)(W_ - 1)) &&
            (y2 >= 0.0f) && (y2 <= (float)(H_ - 1)) &&
            (fabsf(cfx) < (float)W_ * 0.5f) &&
            (fabsf(cfy) < (float)H_ * 0.5f);
        const float validf = valid ? 1.0f : 0.0f;

        const int   ix = __float2int_rd(x2);
        const int   iy = __float2int_rd(y2);
        const float a  = x2 - (float)ix;
        const float bt = y2 - (float)iy;

        const float wTL = (1.0f - a) * (1.0f - bt);
        const float wTR = a * (1.0f - bt);
        const float wBL = (1.0f - a) * bt;
        const float wBR = a * bt;

        // ---- preload 16 filter taps ----
        float f[16];
        const float* fb = fbb + pix;
        #pragma unroll
        for (int t = 0; t < 16; t++) f[t] = __ldcs(fb + t * HW_);

        // ---- window coords, clamped into the staged halo (branchless) ----
        const int ly  = iy - y0 + 5;
        const int lx  = ix - x0 + 5;
        const int lyc = min(max(ly, 0), SH - 5);
        const int lxc = min(max(lx, 0), SWU - 5);
        const bool fixup = valid && ((lyc != ly) || (lxc != lx));

        float r0 = 0.0f, r1 = 0.0f, r2 = 0.0f;

        // ---- fast path: 25 taps, row-pipelined; A: 5 LDS.32, B: 3 LDS.32 ----
        {
            const int base = lyc * PU + lxc;

            unsigned curA[5], nxtA[5];
            unsigned curB[3], nxtB[3];
            #pragma unroll
            for (int c = 0; c < 5; c++) curA[c] = smA[base + c];
            #pragma unroll
            for (int p = 0; p < 3; p++) curB[p] = smB[base + 2 * p];

            #pragma unroll
            for (int r = 0; r < 5; r++) {
                if (r < 4) {
                    const int nb = base + (r + 1) * PU;
                    #pragma unroll
                    for (int c = 0; c < 5; c++) nxtA[c] = smA[nb + c];
                    #pragma unroll
                    for (int p = 0; p < 3; p++) nxtB[p] = smB[nb + 2 * p];
                }

                // per-row weights (fp32)
                float w[5];
                #pragma unroll
                for (int c = 0; c < 5; c++) {
                    float ww = 0.0f;
                    if (r < 4 && c < 4)  ww += wTL * f[r * 4 + c];
                    if (r < 4 && c >= 1) ww += wTR * f[r * 4 + c - 1];
                    if (r >= 1 && c < 4) ww += wBL * f[(r - 1) * 4 + c];
                    if (r >= 1 && c >= 1)ww += wBR * f[(r - 1) * 4 + c - 1];
                    w[c] = ww;
                }

                // channels 0,1: splat weight, HFMA2 against (c0,c1) texel
                __half2 acc01 = __floats2half2_rn(0.0f, 0.0f);
                #pragma unroll
                for (int c = 0; c < 5; c++) {
                    const __half2 tex = *reinterpret_cast<const __half2*>(&curA[c]);
                    acc01 = __hfma2(__float2half2_rn(w[c]), tex, acc01);
                }

                // channel 2: paired taps, weight pairs (w0,w1)(w2,w3)(w4,0)
                __half2 accB = __floats2half2_rn(0.0f, 0.0f);
                {
                    const __half2 wp0 = __floats2half2_rn(w[0], w[1]);
                    const __half2 wp1 = __floats2half2_rn(w[2], w[3]);
                    const __half2 wp2 = __floats2half2_rn(w[4], 0.0f);
                    accB = __hfma2(wp0, *reinterpret_cast<const __half2*>(&curB[0]), accB);
                    accB = __hfma2(wp1, *reinterpret_cast<const __half2*>(&curB[1]), accB);
                    accB = __hfma2(wp2, *reinterpret_cast<const __half2*>(&curB[2]), accB);
                }

                const float2 p01 = __half22float2(acc01);
                const float2 pb  = __half22float2(accB);
                r0 += p01.x;
                r1 += p01.y;
                r2 += pb.x + pb.y;

                if (r < 4) {
                    #pragma unroll
                    for (int c = 0; c < 5; c++) curA[c] = nxtA[c];
                    #pragma unroll
                    for (int p = 0; p < 3; p++) curB[p] = nxtB[p];
                }
            }
        }

        // ---- rare fix-up (warp-uniformly skipped ~always): fp32 global gathers ----
        if (__any_sync(0xffffffffu, fixup)) {
            if (fixup) {
                r0 = 0.0f; r1 = 0.0f; r2 = 0.0f;
                #pragma unroll 1
                for (int r = 0; r < 5; r++) {
                    const int yy = min(max(iy - 1 + r, 0), H_ - 1);
                    const float* g0 = ibase + yy * W_;
                    #pragma unroll 1
                    for (int c = 0; c < 5; c++) {
                        float w = 0.0f;
                        if (r < 4 && c < 4)  w += wTL * f[r * 4 + c];
                        if (r < 4 && c >= 1) w += wTR * f[r * 4 + c - 1];
                        if (r >= 1 && c < 4) w += wBL * f[(r - 1) * 4 + c];
                        if (r >= 1 && c >= 1)w += wBR * f[(r - 1) * 4 + c - 1];

                        const int xo = min(max(ix - 1 + c, 0), W_ - 1);
                        r0 += w * __ldg(g0 + xo);
                        r1 += w * __ldg(g0 + xo + HW_);
                        r2 += w * __ldg(g0 + xo + 2 * HW_);
                    }
                }
            }
        }

        float* ob = obb + pix;
        __stcs(ob,            r0 * validf);
        __stcs(ob + HW_,      r1 * validf);
        __stcs(ob + 2 * HW_,  r2 * validf);
    }
}

extern "C" void kernel_launch(void* const* d_in, const int* in_sizes, int n_in,
                              void* d_out, int out_size)
{
    const float* teninput  = (const float*)d_in[0];
    const float* tenflow   = (const float*)d_in[1];
    const float* tenfilter = (const float*)d_in[2];
    float* out = (float*)d_out;

    dim3 grid(W_ / TW, H_ / TH, B_);   // 15 x 32 x 4
    fi_tiled_h16_kernel<<<grid, NTHREADS>>>(teninput, tenflow, tenfilter, out);
}